// round 7
// baseline (speedup 1.0000x reference)
#include <cuda_runtime.h>
#include <cuda_fp16.h>
#include <cuda_bf16.h>

#define N_NODES 100000
#define N_EDGES 3200000
#define IN_F    256
#define OUT_F   64

// ---------------------------------------------------------------------------
// Scratch (no allocations allowed -> __device__ globals).
// Never passed as kernel args from host; kernels reference them directly.
// ---------------------------------------------------------------------------
__device__ int     g_deg [N_NODES];
__device__ int     g_off [N_NODES + 1];     // scan: start offsets; after k_csr: END offsets
__device__ float   g_norm[N_NODES];
__device__ int     g_esrc[N_EDGES];         // CSR-ordered source ids (by dst)
__device__ __half2 g_featH [N_NODES * 32];  // after GEMM (pre-norm applied)
__device__ __half2 g_feat2H[N_NODES * 32];  // after step 1

// ---------------------------------------------------------------------------
__global__ void k_zero() {
    int i = blockIdx.x * blockDim.x + threadIdx.x;
    if (i < N_NODES) g_deg[i] = 0;
}

__global__ void k_deg(const int* __restrict__ dst) {
    int e = blockIdx.x * blockDim.x + threadIdx.x;
    if (e < N_EDGES) atomicAdd(&g_deg[dst[e]], 1);
}

// ---------------------------------------------------------------------------
// Single-block exclusive scan of degrees -> CSR start offsets; also norm.
// ---------------------------------------------------------------------------
__global__ __launch_bounds__(1024) void k_scan() {
    const int CH = (N_NODES + 1023) / 1024;   // 98
    int t = threadIdx.x;
    int base = t * CH;

    int s = 0;
    for (int i = 0; i < CH; i++) {
        int idx = base + i;
        if (idx < N_NODES) s += g_deg[idx];
    }

    __shared__ int sm[1024];
    sm[t] = s;
    __syncthreads();
    for (int off = 1; off < 1024; off <<= 1) {
        int v = (t >= off) ? sm[t - off] : 0;
        __syncthreads();
        sm[t] += v;
        __syncthreads();
    }
    int excl = sm[t] - s;

    for (int i = 0; i < CH; i++) {
        int idx = base + i;
        if (idx < N_NODES) {
            int d = g_deg[idx];
            g_off[idx] = excl;
            excl += d;
            float df = (float)d;
            g_norm[idx] = rsqrtf(df < 1.0f ? 1.0f : df);
        }
    }
    if (t == 0) g_off[N_NODES] = N_EDGES;
}

// ---------------------------------------------------------------------------
// GEMM: g_featH[n][c] = half( (x[n,:] . W[:,c]) * norm[n] )
// 64x64 tile / block, 256 threads, 4x4 micro-tile per thread, K chunk 64
// ---------------------------------------------------------------------------
#define MT 64
#define KC 64

__global__ __launch_bounds__(256) void k_gemm(const float* __restrict__ x,
                                              const float* __restrict__ W) {
    __shared__ float sx[MT * KC];        // 16 KB
    __shared__ float sw[KC * OUT_F];     // 16 KB

    const int t  = threadIdx.x;
    const int tx = t & 15;
    const int ty = t >> 4;
    const int node0 = blockIdx.x * MT;

    float4 acc0 = make_float4(0.f,0.f,0.f,0.f);
    float4 acc1 = make_float4(0.f,0.f,0.f,0.f);
    float4 acc2 = make_float4(0.f,0.f,0.f,0.f);
    float4 acc3 = make_float4(0.f,0.f,0.f,0.f);

    for (int kc = 0; kc < IN_F; kc += KC) {
        __syncthreads();
        const float4* Wg = (const float4*)(W + (size_t)kc * OUT_F);
        #pragma unroll
        for (int i = 0; i < 4; i++)
            ((float4*)sw)[t + 256 * i] = Wg[t + 256 * i];
        #pragma unroll
        for (int i = 0; i < 4; i++) {
            int idx = t + 256 * i;
            int r   = idx >> 4;
            int c4  = idx & 15;
            int n   = node0 + r;
            float4 v = (n < N_NODES)
                ? *(const float4*)(x + (size_t)n * IN_F + kc + 4 * c4)
                : make_float4(0.f,0.f,0.f,0.f);
            ((float4*)sx)[idx] = v;
        }
        __syncthreads();

        #pragma unroll
        for (int k = 0; k < KC; k += 4) {
            float4 a0 = *(const float4*)(sx + (4*ty+0) * KC + k);
            float4 a1 = *(const float4*)(sx + (4*ty+1) * KC + k);
            float4 a2 = *(const float4*)(sx + (4*ty+2) * KC + k);
            float4 a3 = *(const float4*)(sx + (4*ty+3) * KC + k);
            float4 b0 = *(const float4*)(sw + (k+0) * OUT_F + 4*tx);
            float4 b1 = *(const float4*)(sw + (k+1) * OUT_F + 4*tx);
            float4 b2 = *(const float4*)(sw + (k+2) * OUT_F + 4*tx);
            float4 b3 = *(const float4*)(sw + (k+3) * OUT_F + 4*tx);

            #define FMA4(A, AK, B) \
                A.x = fmaf(AK, B.x, A.x); A.y = fmaf(AK, B.y, A.y); \
                A.z = fmaf(AK, B.z, A.z); A.w = fmaf(AK, B.w, A.w);
            FMA4(acc0, a0.x, b0) FMA4(acc0, a0.y, b1) FMA4(acc0, a0.z, b2) FMA4(acc0, a0.w, b3)
            FMA4(acc1, a1.x, b0) FMA4(acc1, a1.y, b1) FMA4(acc1, a1.z, b2) FMA4(acc1, a1.w, b3)
            FMA4(acc2, a2.x, b0) FMA4(acc2, a2.y, b1) FMA4(acc2, a2.z, b2) FMA4(acc2, a2.w, b3)
            FMA4(acc3, a3.x, b0) FMA4(acc3, a3.y, b1) FMA4(acc3, a3.z, b2) FMA4(acc3, a3.w, b3)
            #undef FMA4
        }
    }

    #pragma unroll
    for (int r = 0; r < 4; r++) {
        int n = node0 + 4*ty + r;
        if (n < N_NODES) {
            float nm = g_norm[n];
            float4 a = r==0 ? acc0 : r==1 ? acc1 : r==2 ? acc2 : acc3;
            g_featH[(size_t)n * 32 + 2*tx    ] = __floats2half2_rn(a.x * nm, a.y * nm);
            g_featH[(size_t)n * 32 + 2*tx + 1] = __floats2half2_rn(a.z * nm, a.w * nm);
        }
    }
}

// ---------------------------------------------------------------------------
// CSR build: pos = atomicAdd(&g_off[d], 1). Afterwards g_off[d] = END of d's
// segment (== start of d+1). Gather recovers start from g_off[node-1].
// ---------------------------------------------------------------------------
__global__ void k_csr(const int* __restrict__ src, const int* __restrict__ dst) {
    int e = blockIdx.x * blockDim.x + threadIdx.x;
    if (e < N_EDGES) {
        int pos = atomicAdd(&g_off[dst[e]], 1);
        g_esrc[pos] = src[e];
    }
}

// ---------------------------------------------------------------------------
// Warp-per-node gather, masked full-width batches: every batch issues 32
// independent row loads (invalid lanes load row 0, weight 0) -> high MLP on
// the remainder too. 8 fp32 accumulator chains.
// ---------------------------------------------------------------------------
__device__ __forceinline__ float2 gather_sum(const __half2* __restrict__ fin,
                                             int start, int end, int lane) {
    float ax=0.f, ay=0.f, bx=0.f, by=0.f, cx=0.f, cy=0.f, dx=0.f, dy=0.f;

    for (int j = start; j < end; j += 32) {
        int rem = end - j;                               // >= 1, warp-uniform
        int myidx = (lane < rem) ? g_esrc[j + lane] : 0;
        #pragma unroll
        for (int tt = 0; tt < 32; tt += 4) {
            int s0 = __shfl_sync(0xffffffffu, myidx, tt);
            int s1 = __shfl_sync(0xffffffffu, myidx, tt + 1);
            int s2 = __shfl_sync(0xffffffffu, myidx, tt + 2);
            int s3 = __shfl_sync(0xffffffffu, myidx, tt + 3);
            float2 v0 = __half22float2(fin[(size_t)s0 * 32 + lane]);
            float2 v1 = __half22float2(fin[(size_t)s1 * 32 + lane]);
            float2 v2 = __half22float2(fin[(size_t)s2 * 32 + lane]);
            float2 v3 = __half22float2(fin[(size_t)s3 * 32 + lane]);
            float w0 = (tt     < rem) ? 1.f : 0.f;
            float w1 = (tt + 1 < rem) ? 1.f : 0.f;
            float w2 = (tt + 2 < rem) ? 1.f : 0.f;
            float w3 = (tt + 3 < rem) ? 1.f : 0.f;
            ax = fmaf(w0, v0.x, ax); ay = fmaf(w0, v0.y, ay);
            bx = fmaf(w1, v1.x, bx); by = fmaf(w1, v1.y, by);
            cx = fmaf(w2, v2.x, cx); cy = fmaf(w2, v2.y, cy);
            dx = fmaf(w3, v3.x, dx); dy = fmaf(w3, v3.y, dy);
        }
    }
    return make_float2((ax + bx) + (cx + dx), (ay + by) + (cy + dy));
}

__device__ __forceinline__ void node_range(int node, int& start, int& end) {
    // after k_csr, g_off[d] = end of segment d; start = end of d-1 (or 0)
    start = (node == 0) ? 0 : g_off[node - 1];
    end   = g_off[node];
}

// Step 1: g_feat2H[n] = half( norm^2 * sum g_featH[esrc] )
__global__ __launch_bounds__(256) void k_gather1() {
    int node = (blockIdx.x * 256 + threadIdx.x) >> 5;
    if (node >= N_NODES) return;
    int lane = threadIdx.x & 31;
    int start, end; node_range(node, start, end);
    float2 s = gather_sum(g_featH, start, end, lane);
    float nm = g_norm[node];
    float f = nm * nm;
    g_feat2H[(size_t)node * 32 + lane] = __floats2half2_rn(s.x * f, s.y * f);
}

// Step 2: out[n] = norm * sum g_feat2H[esrc] + b   (fp32 out)
__global__ __launch_bounds__(256) void k_gather2(float* __restrict__ out,
                                                 const float* __restrict__ bias) {
    int node = (blockIdx.x * 256 + threadIdx.x) >> 5;
    if (node >= N_NODES) return;
    int lane = threadIdx.x & 31;
    int start, end; node_range(node, start, end);
    float2 s = gather_sum(g_feat2H, start, end, lane);
    float nm = g_norm[node];
    float2 r;
    r.x = fmaf(s.x, nm, bias[2 * lane]);
    r.y = fmaf(s.y, nm, bias[2 * lane + 1]);
    ((float2*)out)[(size_t)node * 32 + lane] = r;
}

// ---------------------------------------------------------------------------
// Launch. gemm in launch slot #4 (profiled slot) — needs only k_scan.
// ---------------------------------------------------------------------------
extern "C" void kernel_launch(void* const* d_in, const int* in_sizes, int n_in,
                              void* d_out, int out_size) {
    const float* x   = (const float*)d_in[0];
    const int*   src = (const int*)  d_in[1];
    const int*   dst = (const int*)  d_in[2];
    const float* W   = (const float*)d_in[3];
    const float* b   = (const float*)d_in[4];
    float*       out = (float*)d_out;

    k_zero<<<(N_NODES + 255) / 256, 256>>>();
    k_deg <<<(N_EDGES + 255) / 256, 256>>>(dst);
    k_scan<<<1, 1024>>>();
    k_gemm<<<(N_NODES + MT - 1) / MT, 256>>>(x, W);   // slot 4 (profiled)
    k_csr <<<(N_EDGES + 255) / 256, 256>>>(src, dst);

    int gather_blocks = (N_NODES * 32 + 255) / 256;   // warp per node
    k_gather1<<<gather_blocks, 256>>>();
    k_gather2<<<gather_blocks, 256>>>(out, b);
}

// round 8
// speedup vs baseline: 1.1418x; 1.1418x over previous
#include <cuda_runtime.h>
#include <cuda_fp16.h>
#include <cuda_bf16.h>

#define N_NODES 100000
#define N_EDGES 3200000
#define IN_F    256
#define OUT_F   64

// ---------------------------------------------------------------------------
// Scratch (no allocations allowed -> __device__ globals).
// Never passed as kernel args from host; kernels reference them directly.
// ---------------------------------------------------------------------------
__device__ int     g_deg [N_NODES];
__device__ int     g_off [N_NODES + 1];     // scan: start offsets; after k_csr: END offsets
__device__ float   g_norm[N_NODES];
__device__ int     g_esrc[N_EDGES];         // CSR-ordered source ids (by dst)
__device__ __half2 g_featH [N_NODES * 32];  // after GEMM (pre-norm applied), 128B/row
__device__ __half2 g_feat2H[N_NODES * 32];  // after step 1

// ---------------------------------------------------------------------------
__global__ void k_zero() {
    int i = blockIdx.x * blockDim.x + threadIdx.x;
    if (i < N_NODES) g_deg[i] = 0;
}

__global__ void k_deg(const int* __restrict__ dst) {
    int e = blockIdx.x * blockDim.x + threadIdx.x;
    if (e < N_EDGES) atomicAdd(&g_deg[dst[e]], 1);
}

// ---------------------------------------------------------------------------
// Single-block exclusive scan of degrees -> CSR start offsets; also norm.
// ---------------------------------------------------------------------------
__global__ __launch_bounds__(1024) void k_scan() {
    const int CH = (N_NODES + 1023) / 1024;   // 98
    int t = threadIdx.x;
    int base = t * CH;

    int s = 0;
    for (int i = 0; i < CH; i++) {
        int idx = base + i;
        if (idx < N_NODES) s += g_deg[idx];
    }

    __shared__ int sm[1024];
    sm[t] = s;
    __syncthreads();
    for (int off = 1; off < 1024; off <<= 1) {
        int v = (t >= off) ? sm[t - off] : 0;
        __syncthreads();
        sm[t] += v;
        __syncthreads();
    }
    int excl = sm[t] - s;

    for (int i = 0; i < CH; i++) {
        int idx = base + i;
        if (idx < N_NODES) {
            int d = g_deg[idx];
            g_off[idx] = excl;
            excl += d;
            float df = (float)d;
            g_norm[idx] = rsqrtf(df < 1.0f ? 1.0f : df);
        }
    }
    if (t == 0) g_off[N_NODES] = N_EDGES;
}

// ---------------------------------------------------------------------------
// GEMM: g_featH[n][c] = half( (x[n,:] . W[:,c]) * norm[n] )
// 64x64 tile / block, 256 threads, 4x4 micro-tile per thread, K chunk 64.
// Measured at 97.8us = fp32 FFMA roofline for 3.28 GFLOP.
// ---------------------------------------------------------------------------
#define MT 64
#define KC 64

__global__ __launch_bounds__(256) void k_gemm(const float* __restrict__ x,
                                              const float* __restrict__ W) {
    __shared__ float sx[MT * KC];        // 16 KB
    __shared__ float sw[KC * OUT_F];     // 16 KB

    const int t  = threadIdx.x;
    const int tx = t & 15;
    const int ty = t >> 4;
    const int node0 = blockIdx.x * MT;

    float4 acc0 = make_float4(0.f,0.f,0.f,0.f);
    float4 acc1 = make_float4(0.f,0.f,0.f,0.f);
    float4 acc2 = make_float4(0.f,0.f,0.f,0.f);
    float4 acc3 = make_float4(0.f,0.f,0.f,0.f);

    for (int kc = 0; kc < IN_F; kc += KC) {
        __syncthreads();
        const float4* Wg = (const float4*)(W + (size_t)kc * OUT_F);
        #pragma unroll
        for (int i = 0; i < 4; i++)
            ((float4*)sw)[t + 256 * i] = Wg[t + 256 * i];
        #pragma unroll
        for (int i = 0; i < 4; i++) {
            int idx = t + 256 * i;
            int r   = idx >> 4;
            int c4  = idx & 15;
            int n   = node0 + r;
            float4 v = (n < N_NODES)
                ? *(const float4*)(x + (size_t)n * IN_F + kc + 4 * c4)
                : make_float4(0.f,0.f,0.f,0.f);
            ((float4*)sx)[idx] = v;
        }
        __syncthreads();

        #pragma unroll
        for (int k = 0; k < KC; k += 4) {
            float4 a0 = *(const float4*)(sx + (4*ty+0) * KC + k);
            float4 a1 = *(const float4*)(sx + (4*ty+1) * KC + k);
            float4 a2 = *(const float4*)(sx + (4*ty+2) * KC + k);
            float4 a3 = *(const float4*)(sx + (4*ty+3) * KC + k);
            float4 b0 = *(const float4*)(sw + (k+0) * OUT_F + 4*tx);
            float4 b1 = *(const float4*)(sw + (k+1) * OUT_F + 4*tx);
            float4 b2 = *(const float4*)(sw + (k+2) * OUT_F + 4*tx);
            float4 b3 = *(const float4*)(sw + (k+3) * OUT_F + 4*tx);

            #define FMA4(A, AK, B) \
                A.x = fmaf(AK, B.x, A.x); A.y = fmaf(AK, B.y, A.y); \
                A.z = fmaf(AK, B.z, A.z); A.w = fmaf(AK, B.w, A.w);
            FMA4(acc0, a0.x, b0) FMA4(acc0, a0.y, b1) FMA4(acc0, a0.z, b2) FMA4(acc0, a0.w, b3)
            FMA4(acc1, a1.x, b0) FMA4(acc1, a1.y, b1) FMA4(acc1, a1.z, b2) FMA4(acc1, a1.w, b3)
            FMA4(acc2, a2.x, b0) FMA4(acc2, a2.y, b1) FMA4(acc2, a2.z, b2) FMA4(acc2, a2.w, b3)
            FMA4(acc3, a3.x, b0) FMA4(acc3, a3.y, b1) FMA4(acc3, a3.z, b2) FMA4(acc3, a3.w, b3)
            #undef FMA4
        }
    }

    #pragma unroll
    for (int r = 0; r < 4; r++) {
        int n = node0 + 4*ty + r;
        if (n < N_NODES) {
            float nm = g_norm[n];
            float4 a = r==0 ? acc0 : r==1 ? acc1 : r==2 ? acc2 : acc3;
            g_featH[(size_t)n * 32 + 2*tx    ] = __floats2half2_rn(a.x * nm, a.y * nm);
            g_featH[(size_t)n * 32 + 2*tx + 1] = __floats2half2_rn(a.z * nm, a.w * nm);
        }
    }
}

// ---------------------------------------------------------------------------
// CSR build: pos = atomicAdd(&g_off[d], 1). Afterwards g_off[d] = END of d's
// segment; gather recovers start from g_off[node-1].
// ---------------------------------------------------------------------------
__global__ void k_csr(const int* __restrict__ src, const int* __restrict__ dst) {
    int e = blockIdx.x * blockDim.x + threadIdx.x;
    if (e < N_EDGES) {
        int pos = atomicAdd(&g_off[dst[e]], 1);
        g_esrc[pos] = src[e];
    }
}

// ---------------------------------------------------------------------------
// Warp-per-node gather, 4 edges per LDG.128:
// fp16 row = 128B = 8 lanes x uint4, so one warp-wide LDG.128 covers 4 rows.
// Per 32-edge batch: 1 idx LDG + 8 SHFL.IDX + 8 LDG.128 (vs 65 LSU ops before).
// Lane accumulates 8 fp32 cols for its lane-group's edges; cross-group
// shfl_xor(8,16) reduction at the end. Tail edges masked with weight-0 fmaf.
// ---------------------------------------------------------------------------
__device__ __forceinline__ void gather_core(const uint4* __restrict__ fin,
                                            int start, int end, int lane,
                                            float* acc) {
    const int slot = lane >> 3;          // which of 4 edges this lane serves
    const int col8 = lane & 7;           // which 16B chunk of the 128B row

    for (int j = start; j < end; j += 32) {
        int rem = end - j;                                   // >= 1, warp-uniform
        int myidx = (lane < rem) ? g_esrc[j + lane] : 0;
        #pragma unroll
        for (int it = 0; it < 8; it++) {
            int es   = it * 4 + slot;                        // edge slot 0..31
            int sidx = __shfl_sync(0xffffffffu, myidx, es);  // row id for my group
            uint4 v  = fin[(size_t)sidx * 8 + col8];
            float w  = (es < rem) ? 1.f : 0.f;
            float2 p0 = __half22float2(*reinterpret_cast<__half2*>(&v.x));
            float2 p1 = __half22float2(*reinterpret_cast<__half2*>(&v.y));
            float2 p2 = __half22float2(*reinterpret_cast<__half2*>(&v.z));
            float2 p3 = __half22float2(*reinterpret_cast<__half2*>(&v.w));
            acc[0] = fmaf(w, p0.x, acc[0]);
            acc[1] = fmaf(w, p0.y, acc[1]);
            acc[2] = fmaf(w, p1.x, acc[2]);
            acc[3] = fmaf(w, p1.y, acc[3]);
            acc[4] = fmaf(w, p2.x, acc[4]);
            acc[5] = fmaf(w, p2.y, acc[5]);
            acc[6] = fmaf(w, p3.x, acc[6]);
            acc[7] = fmaf(w, p3.y, acc[7]);
        }
    }

    // Reduce the 4 lane-groups: lanes sharing (lane&7) hold the same cols.
    #pragma unroll
    for (int k = 0; k < 8; k++) {
        acc[k] += __shfl_xor_sync(0xffffffffu, acc[k], 8);
        acc[k] += __shfl_xor_sync(0xffffffffu, acc[k], 16);
    }
}

__device__ __forceinline__ void node_range(int node, int& start, int& end) {
    start = (node == 0) ? 0 : g_off[node - 1];
    end   = g_off[node];
}

// Step 1: g_feat2H[n] = half( norm^2 * sum g_featH[esrc] )
__global__ __launch_bounds__(256) void k_gather1() {
    int node = (blockIdx.x * 256 + threadIdx.x) >> 5;
    if (node >= N_NODES) return;
    int lane = threadIdx.x & 31;
    int start, end; node_range(node, start, end);

    float acc[8] = {0.f,0.f,0.f,0.f,0.f,0.f,0.f,0.f};
    gather_core((const uint4*)g_featH, start, end, lane, acc);

    if (lane < 8) {                      // lane l owns cols 8l..8l+7
        float nm = g_norm[node];
        float f  = nm * nm;
        uint4 o;
        __half2 h;
        h = __floats2half2_rn(acc[0]*f, acc[1]*f); o.x = *reinterpret_cast<unsigned*>(&h);
        h = __floats2half2_rn(acc[2]*f, acc[3]*f); o.y = *reinterpret_cast<unsigned*>(&h);
        h = __floats2half2_rn(acc[4]*f, acc[5]*f); o.z = *reinterpret_cast<unsigned*>(&h);
        h = __floats2half2_rn(acc[6]*f, acc[7]*f); o.w = *reinterpret_cast<unsigned*>(&h);
        ((uint4*)g_feat2H)[(size_t)node * 8 + lane] = o;
    }
}

// Step 2: out[n] = norm * sum g_feat2H[esrc] + b   (fp32 out)
__global__ __launch_bounds__(256) void k_gather2(float* __restrict__ out,
                                                 const float* __restrict__ bias) {
    int node = (blockIdx.x * 256 + threadIdx.x) >> 5;
    if (node >= N_NODES) return;
    int lane = threadIdx.x & 31;
    int start, end; node_range(node, start, end);

    float acc[8] = {0.f,0.f,0.f,0.f,0.f,0.f,0.f,0.f};
    gather_core((const uint4*)g_feat2H, start, end, lane, acc);

    if (lane < 8) {                      // lane l owns cols 8l..8l+7
        float nm = g_norm[node];
        const float4* b4 = (const float4*)bias;
        float4 bb0 = b4[lane * 2];
        float4 bb1 = b4[lane * 2 + 1];
        float4 r0, r1;
        r0.x = fmaf(acc[0], nm, bb0.x);
        r0.y = fmaf(acc[1], nm, bb0.y);
        r0.z = fmaf(acc[2], nm, bb0.z);
        r0.w = fmaf(acc[3], nm, bb0.w);
        r1.x = fmaf(acc[4], nm, bb1.x);
        r1.y = fmaf(acc[5], nm, bb1.y);
        r1.z = fmaf(acc[6], nm, bb1.z);
        r1.w = fmaf(acc[7], nm, bb1.w);
        float4* o4 = (float4*)out;
        o4[(size_t)node * 16 + lane * 2    ] = r0;
        o4[(size_t)node * 16 + lane * 2 + 1] = r1;
    }
}

// ---------------------------------------------------------------------------
// Launch: inputs are x, src, dst, W, b (metadata order)
// ---------------------------------------------------------------------------
extern "C" void kernel_launch(void* const* d_in, const int* in_sizes, int n_in,
                              void* d_out, int out_size) {
    const float* x   = (const float*)d_in[0];
    const int*   src = (const int*)  d_in[1];
    const int*   dst = (const int*)  d_in[2];
    const float* W   = (const float*)d_in[3];
    const float* b   = (const float*)d_in[4];
    float*       out = (float*)d_out;

    k_zero<<<(N_NODES + 255) / 256, 256>>>();
    k_deg <<<(N_EDGES + 255) / 256, 256>>>(dst);
    k_scan<<<1, 1024>>>();
    k_gemm<<<(N_NODES + MT - 1) / MT, 256>>>(x, W);   // slot 4 (profiled)
    k_csr <<<(N_EDGES + 255) / 256, 256>>>(src, dst);

    int gather_blocks = (N_NODES * 32 + 255) / 256;   // warp per node
    k_gather1<<<gather_blocks, 256>>>();
    k_gather2<<<gather_blocks, 256>>>(out, b);
}

// round 9
// speedup vs baseline: 1.1666x; 1.0217x over previous
#include <cuda_runtime.h>
#include <cuda_fp16.h>
#include <cuda_bf16.h>

#define N_NODES 100000
#define N_EDGES 3200000
#define IN_F    256
#define OUT_F   64

// ---------------------------------------------------------------------------
// Scratch (no allocations -> __device__ globals, zero-initialized at load).
// Never passed as kernel args from host; kernels reference them directly.
// g_deg is zeroed at the END of each call (top of k_gather2) for the next
// call; the first call relies on static zero-init. Same work every call.
// ---------------------------------------------------------------------------
__device__ int     g_deg [N_NODES];
__device__ int     g_off [N_NODES + 1];     // scan: start offsets; after csr: END offsets
__device__ float   g_norm[N_NODES];
__device__ int     g_esrc[N_EDGES];         // CSR-ordered source ids (by dst)
__device__ __half2 g_featH [N_NODES * 32];  // after GEMM (pre-norm applied), 128B/row
__device__ __half2 g_feat2H[N_NODES * 32];  // after step 1

// ---------------------------------------------------------------------------
__global__ void k_deg(const int* __restrict__ dst) {
    int e = blockIdx.x * blockDim.x + threadIdx.x;
    if (e < N_EDGES) atomicAdd(&g_deg[dst[e]], 1);
}

// ---------------------------------------------------------------------------
// Single-block exclusive scan of degrees -> CSR start offsets; also norm.
// ---------------------------------------------------------------------------
__global__ __launch_bounds__(1024) void k_scan() {
    const int CH = (N_NODES + 1023) / 1024;   // 98
    int t = threadIdx.x;
    int base = t * CH;

    int s = 0;
    for (int i = 0; i < CH; i++) {
        int idx = base + i;
        if (idx < N_NODES) s += g_deg[idx];
    }

    __shared__ int sm[1024];
    sm[t] = s;
    __syncthreads();
    for (int off = 1; off < 1024; off <<= 1) {
        int v = (t >= off) ? sm[t - off] : 0;
        __syncthreads();
        sm[t] += v;
        __syncthreads();
    }
    int excl = sm[t] - s;

    for (int i = 0; i < CH; i++) {
        int idx = base + i;
        if (idx < N_NODES) {
            int d = g_deg[idx];
            g_off[idx] = excl;
            excl += d;
            float df = (float)d;
            g_norm[idx] = rsqrtf(df < 1.0f ? 1.0f : df);
        }
    }
    if (t == 0) g_off[N_NODES] = N_EDGES;
}

// ---------------------------------------------------------------------------
// Fused GEMM + CSR-build. Both depend only on k_scan; independent of each
// other -> co-resident blocks overlap fma-bound GEMM with memory-bound CSR.
//   blocks [0, GEMM_BLOCKS):          64x64 GEMM tile (4x4 micro-tile/thread)
//   blocks [GEMM_BLOCKS, +CSR_BLOCKS): edge placement via atomicAdd on g_off
// After this kernel g_off[d] = END of segment d.
// ---------------------------------------------------------------------------
#define MT 64
#define KC 64
#define GEMM_BLOCKS ((N_NODES + MT - 1) / MT)        // 1563
#define CSR_BLOCKS  ((N_EDGES + 255) / 256)          // 12500

__global__ __launch_bounds__(256) void k_gemm_csr(const float* __restrict__ x,
                                                  const float* __restrict__ W,
                                                  const int* __restrict__ src,
                                                  const int* __restrict__ dst) {
    __shared__ float sx[MT * KC];        // 16 KB
    __shared__ float sw[KC * OUT_F];     // 16 KB

    if (blockIdx.x >= GEMM_BLOCKS) {
        // ---- CSR branch ----
        int e = (blockIdx.x - GEMM_BLOCKS) * 256 + threadIdx.x;
        if (e < N_EDGES) {
            int pos = atomicAdd(&g_off[dst[e]], 1);
            g_esrc[pos] = src[e];
        }
        return;
    }

    // ---- GEMM branch ----
    const int t  = threadIdx.x;
    const int tx = t & 15;
    const int ty = t >> 4;
    const int node0 = blockIdx.x * MT;

    float4 acc0 = make_float4(0.f,0.f,0.f,0.f);
    float4 acc1 = make_float4(0.f,0.f,0.f,0.f);
    float4 acc2 = make_float4(0.f,0.f,0.f,0.f);
    float4 acc3 = make_float4(0.f,0.f,0.f,0.f);

    for (int kc = 0; kc < IN_F; kc += KC) {
        __syncthreads();
        const float4* Wg = (const float4*)(W + (size_t)kc * OUT_F);
        #pragma unroll
        for (int i = 0; i < 4; i++)
            ((float4*)sw)[t + 256 * i] = Wg[t + 256 * i];
        #pragma unroll
        for (int i = 0; i < 4; i++) {
            int idx = t + 256 * i;
            int r   = idx >> 4;
            int c4  = idx & 15;
            int n   = node0 + r;
            float4 v = (n < N_NODES)
                ? *(const float4*)(x + (size_t)n * IN_F + kc + 4 * c4)
                : make_float4(0.f,0.f,0.f,0.f);
            ((float4*)sx)[idx] = v;
        }
        __syncthreads();

        #pragma unroll
        for (int k = 0; k < KC; k += 4) {
            float4 a0 = *(const float4*)(sx + (4*ty+0) * KC + k);
            float4 a1 = *(const float4*)(sx + (4*ty+1) * KC + k);
            float4 a2 = *(const float4*)(sx + (4*ty+2) * KC + k);
            float4 a3 = *(const float4*)(sx + (4*ty+3) * KC + k);
            float4 b0 = *(const float4*)(sw + (k+0) * OUT_F + 4*tx);
            float4 b1 = *(const float4*)(sw + (k+1) * OUT_F + 4*tx);
            float4 b2 = *(const float4*)(sw + (k+2) * OUT_F + 4*tx);
            float4 b3 = *(const float4*)(sw + (k+3) * OUT_F + 4*tx);

            #define FMA4(A, AK, B) \
                A.x = fmaf(AK, B.x, A.x); A.y = fmaf(AK, B.y, A.y); \
                A.z = fmaf(AK, B.z, A.z); A.w = fmaf(AK, B.w, A.w);
            FMA4(acc0, a0.x, b0) FMA4(acc0, a0.y, b1) FMA4(acc0, a0.z, b2) FMA4(acc0, a0.w, b3)
            FMA4(acc1, a1.x, b0) FMA4(acc1, a1.y, b1) FMA4(acc1, a1.z, b2) FMA4(acc1, a1.w, b3)
            FMA4(acc2, a2.x, b0) FMA4(acc2, a2.y, b1) FMA4(acc2, a2.z, b2) FMA4(acc2, a2.w, b3)
            FMA4(acc3, a3.x, b0) FMA4(acc3, a3.y, b1) FMA4(acc3, a3.z, b2) FMA4(acc3, a3.w, b3)
            #undef FMA4
        }
    }

    #pragma unroll
    for (int r = 0; r < 4; r++) {
        int n = node0 + 4*ty + r;
        if (n < N_NODES) {
            float nm = g_norm[n];
            float4 a = r==0 ? acc0 : r==1 ? acc1 : r==2 ? acc2 : acc3;
            g_featH[(size_t)n * 32 + 2*tx    ] = __floats2half2_rn(a.x * nm, a.y * nm);
            g_featH[(size_t)n * 32 + 2*tx + 1] = __floats2half2_rn(a.z * nm, a.w * nm);
        }
    }
}

// ---------------------------------------------------------------------------
// Warp-per-node gather, 4 edges per LDG.128 (identical to round 8):
// fp16 row = 128B = 8 lanes x uint4; one warp-wide LDG.128 covers 4 rows.
// ---------------------------------------------------------------------------
__device__ __forceinline__ void gather_core(const uint4* __restrict__ fin,
                                            int start, int end, int lane,
                                            float* acc) {
    const int slot = lane >> 3;          // which of 4 edges this lane serves
    const int col8 = lane & 7;           // which 16B chunk of the 128B row

    for (int j = start; j < end; j += 32) {
        int rem = end - j;                                   // >= 1, warp-uniform
        int myidx = (lane < rem) ? g_esrc[j + lane] : 0;
        #pragma unroll
        for (int it = 0; it < 8; it++) {
            int es   = it * 4 + slot;                        // edge slot 0..31
            int sidx = __shfl_sync(0xffffffffu, myidx, es);  // row id for my group
            uint4 v  = fin[(size_t)sidx * 8 + col8];
            float w  = (es < rem) ? 1.f : 0.f;
            float2 p0 = __half22float2(*reinterpret_cast<__half2*>(&v.x));
            float2 p1 = __half22float2(*reinterpret_cast<__half2*>(&v.y));
            float2 p2 = __half22float2(*reinterpret_cast<__half2*>(&v.z));
            float2 p3 = __half22float2(*reinterpret_cast<__half2*>(&v.w));
            acc[0] = fmaf(w, p0.x, acc[0]);
            acc[1] = fmaf(w, p0.y, acc[1]);
            acc[2] = fmaf(w, p1.x, acc[2]);
            acc[3] = fmaf(w, p1.y, acc[3]);
            acc[4] = fmaf(w, p2.x, acc[4]);
            acc[5] = fmaf(w, p2.y, acc[5]);
            acc[6] = fmaf(w, p3.x, acc[6]);
            acc[7] = fmaf(w, p3.y, acc[7]);
        }
    }

    // Reduce the 4 lane-groups: lanes sharing (lane&7) hold the same cols.
    #pragma unroll
    for (int k = 0; k < 8; k++) {
        acc[k] += __shfl_xor_sync(0xffffffffu, acc[k], 8);
        acc[k] += __shfl_xor_sync(0xffffffffu, acc[k], 16);
    }
}

__device__ __forceinline__ void node_range(int node, int& start, int& end) {
    start = (node == 0) ? 0 : g_off[node - 1];
    end   = g_off[node];
}

// Step 1: g_feat2H[n] = half( norm^2 * sum g_featH[esrc] )   [PROFILED SLOT 4]
__global__ __launch_bounds__(256) void k_gather1() {
    int node = (blockIdx.x * 256 + threadIdx.x) >> 5;
    if (node >= N_NODES) return;
    int lane = threadIdx.x & 31;
    int start, end; node_range(node, start, end);

    float acc[8] = {0.f,0.f,0.f,0.f,0.f,0.f,0.f,0.f};
    gather_core((const uint4*)g_featH, start, end, lane, acc);

    if (lane < 8) {                      // lane l owns cols 8l..8l+7
        float nm = g_norm[node];
        float f  = nm * nm;
        uint4 o;
        __half2 h;
        h = __floats2half2_rn(acc[0]*f, acc[1]*f); o.x = *reinterpret_cast<unsigned*>(&h);
        h = __floats2half2_rn(acc[2]*f, acc[3]*f); o.y = *reinterpret_cast<unsigned*>(&h);
        h = __floats2half2_rn(acc[4]*f, acc[5]*f); o.z = *reinterpret_cast<unsigned*>(&h);
        h = __floats2half2_rn(acc[6]*f, acc[7]*f); o.w = *reinterpret_cast<unsigned*>(&h);
        ((uint4*)g_feat2H)[(size_t)node * 8 + lane] = o;
    }
}

// Step 2: out[n] = norm * sum g_feat2H[esrc] + b   (fp32 out)
// Also zeroes g_deg for the NEXT call (g_deg unused by this kernel).
__global__ __launch_bounds__(256) void k_gather2(float* __restrict__ out,
                                                 const float* __restrict__ bias) {
    int gtid = blockIdx.x * 256 + threadIdx.x;
    if (gtid < N_NODES) g_deg[gtid] = 0;          // prep next call (before any return)

    int node = gtid >> 5;
    if (node >= N_NODES) return;
    int lane = threadIdx.x & 31;
    int start, end; node_range(node, start, end);

    float acc[8] = {0.f,0.f,0.f,0.f,0.f,0.f,0.f,0.f};
    gather_core((const uint4*)g_feat2H, start, end, lane, acc);

    if (lane < 8) {                      // lane l owns cols 8l..8l+7
        float nm = g_norm[node];
        const float4* b4 = (const float4*)bias;
        float4 bb0 = b4[lane * 2];
        float4 bb1 = b4[lane * 2 + 1];
        float4 r0, r1;
        r0.x = fmaf(acc[0], nm, bb0.x);
        r0.y = fmaf(acc[1], nm, bb0.y);
        r0.z = fmaf(acc[2], nm, bb0.z);
        r0.w = fmaf(acc[3], nm, bb0.w);
        r1.x = fmaf(acc[4], nm, bb1.x);
        r1.y = fmaf(acc[5], nm, bb1.y);
        r1.z = fmaf(acc[6], nm, bb1.z);
        r1.w = fmaf(acc[7], nm, bb1.w);
        float4* o4 = (float4*)out;
        o4[(size_t)node * 16 + lane * 2    ] = r0;
        o4[(size_t)node * 16 + lane * 2 + 1] = r1;
    }
}

// ---------------------------------------------------------------------------
// Launch: inputs are x, src, dst, W, b (metadata order).
// Order: deg(1), scan(2), gemm_csr(3), gather1(4 <- profiled), gather2(5).
// ---------------------------------------------------------------------------
extern "C" void kernel_launch(void* const* d_in, const int* in_sizes, int n_in,
                              void* d_out, int out_size) {
    const float* x   = (const float*)d_in[0];
    const int*   src = (const int*)  d_in[1];
    const int*   dst = (const int*)  d_in[2];
    const float* W   = (const float*)d_in[3];
    const float* b   = (const float*)d_in[4];
    float*       out = (float*)d_out;

    k_deg <<<(N_EDGES + 255) / 256, 256>>>(dst);
    k_scan<<<1, 1024>>>();
    k_gemm_csr<<<GEMM_BLOCKS + CSR_BLOCKS, 256>>>(x, W, src, dst);

    int gather_blocks = (N_NODES * 32 + 255) / 256;   // warp per node
    k_gather1<<<gather_blocks, 256>>>();
    k_gather2<<<gather_blocks, 256>>>(out, b);
}

// round 11
// speedup vs baseline: 1.5946x; 1.3669x over previous
#include <cuda_runtime.h>
#include <cuda_fp16.h>
#include <cuda_bf16.h>

#define N_NODES 100000
#define N_EDGES 3200000
#define IN_F    256
#define OUT_F   64

// Padded node-array length: 1024 scan threads * 100 nodes each, so the scan
// runs guard-free with int4/float4 vector accesses.
#define NPAD    102400

// ---------------------------------------------------------------------------
// Scratch (no allocations -> __device__ globals). Never passed as kernel args
// from host (host symbol is a shadow); kernels reference them directly.
// ---------------------------------------------------------------------------
__device__ __align__(16) int     g_deg [NPAD];
__device__ __align__(16) int     g_off [NPAD + 4]; // after csr: END offsets
__device__ __align__(16) float   g_norm[NPAD];
__device__ int     g_esrc[N_EDGES];                // CSR-ordered source ids (by dst)
__device__ __half2 g_featH [N_NODES * 32];         // after GEMM, 128B/row
__device__ __half2 g_feat2H[N_NODES * 32];         // after step 1

// ---------------------------------------------------------------------------
// 1) zero padded degree array (graph replays re-run everything)
// ---------------------------------------------------------------------------
__global__ void k_zero() {
    int i = blockIdx.x * blockDim.x + threadIdx.x;   // over NPAD/4 int4s
    if (i < NPAD / 4) ((int4*)g_deg)[i] = make_int4(0, 0, 0, 0);
}

// 2) in-degrees
__global__ void k_deg(const int* __restrict__ dst) {
    int e = blockIdx.x * blockDim.x + threadIdx.x;
    if (e < N_EDGES) atomicAdd(&g_deg[dst[e]], 1);
}

// ---------------------------------------------------------------------------
// 3) single-block scan, branch-free + vectorized: thread t owns nodes
// [100t, 100t+100). Pass 1: int4 sums (MLP 25). Hillis-Steele across 1024.
// Pass 2: int4 reload (L1-hot) -> offsets + norm, int4/float4 stores.
// Padded degrees are 0 -> offsets beyond N_NODES all equal N_EDGES (harmless).
// ---------------------------------------------------------------------------
__global__ __launch_bounds__(1024) void k_scan() {
    int t = threadIdx.x;
    int base = t * 100;
    const int4* d4 = (const int4*)(g_deg + base);

    int s = 0;
    #pragma unroll
    for (int i = 0; i < 25; i++) {
        int4 v = d4[i];
        s += v.x + v.y + v.z + v.w;
    }

    __shared__ int sm[1024];
    sm[t] = s;
    __syncthreads();
    for (int off = 1; off < 1024; off <<= 1) {
        int v = (t >= off) ? sm[t - off] : 0;
        __syncthreads();
        sm[t] += v;
        __syncthreads();
    }
    int excl = sm[t] - s;

    int4*   o4 = (int4*)  (g_off  + base);
    float4* n4 = (float4*)(g_norm + base);
    #pragma unroll
    for (int i = 0; i < 25; i++) {
        int4 v = d4[i];
        int4 o; float4 nm;
        o.x = excl; nm.x = rsqrtf(fmaxf((float)v.x, 1.f)); excl += v.x;
        o.y = excl; nm.y = rsqrtf(fmaxf((float)v.y, 1.f)); excl += v.y;
        o.z = excl; nm.z = rsqrtf(fmaxf((float)v.z, 1.f)); excl += v.z;
        o.w = excl; nm.w = rsqrtf(fmaxf((float)v.w, 1.f)); excl += v.w;
        o4[i] = o; n4[i] = nm;
    }
    // NOTE: o.x here is the EXCLUSIVE start of node base+4i; k_csr's atomicAdd
    // turns g_off[d] into the END of segment d, as node_range expects.
}

// ---------------------------------------------------------------------------
// 4) fused GEMM + CSR, 1:8 INTERLEAVED so both kinds co-reside on every SM:
//    bid % 9 == 0  -> GEMM tile bid/9      (1563 tiles)
//    else          -> CSR chunk bid/9*8+(bid%9-1)  (12500 chunks, guarded)
// ---------------------------------------------------------------------------
#define MT 64
#define KC 64
#define GEMM_BLOCKS ((N_NODES + MT - 1) / MT)        // 1563
#define FUSED_BLOCKS (GEMM_BLOCKS * 9)               // 14067

__global__ __launch_bounds__(256) void k_gemm_csr(const float* __restrict__ x,
                                                  const float* __restrict__ W,
                                                  const int* __restrict__ src,
                                                  const int* __restrict__ dst) {
    __shared__ float sx[MT * KC];        // 16 KB
    __shared__ float sw[KC * OUT_F];     // 16 KB

    const int q = blockIdx.x / 9;
    const int r = blockIdx.x % 9;

    if (r != 0) {
        // ---- CSR branch ----
        int e = (q * 8 + (r - 1)) * 256 + threadIdx.x;
        if (e < N_EDGES) {
            int pos = atomicAdd(&g_off[dst[e]], 1);
            g_esrc[pos] = src[e];
        }
        return;
    }

    // ---- GEMM branch: tile q ----
    const int t  = threadIdx.x;
    const int tx = t & 15;
    const int ty = t >> 4;
    const int node0 = q * MT;

    float4 acc0 = make_float4(0.f,0.f,0.f,0.f);
    float4 acc1 = make_float4(0.f,0.f,0.f,0.f);
    float4 acc2 = make_float4(0.f,0.f,0.f,0.f);
    float4 acc3 = make_float4(0.f,0.f,0.f,0.f);

    for (int kc = 0; kc < IN_F; kc += KC) {
        __syncthreads();
        const float4* Wg = (const float4*)(W + (size_t)kc * OUT_F);
        #pragma unroll
        for (int i = 0; i < 4; i++)
            ((float4*)sw)[t + 256 * i] = Wg[t + 256 * i];
        #pragma unroll
        for (int i = 0; i < 4; i++) {
            int idx = t + 256 * i;
            int rr  = idx >> 4;
            int c4  = idx & 15;
            int n   = node0 + rr;
            float4 v = (n < N_NODES)
                ? *(const float4*)(x + (size_t)n * IN_F + kc + 4 * c4)
                : make_float4(0.f,0.f,0.f,0.f);
            ((float4*)sx)[idx] = v;
        }
        __syncthreads();

        #pragma unroll
        for (int k = 0; k < KC; k += 4) {
            float4 a0 = *(const float4*)(sx + (4*ty+0) * KC + k);
            float4 a1 = *(const float4*)(sx + (4*ty+1) * KC + k);
            float4 a2 = *(const float4*)(sx + (4*ty+2) * KC + k);
            float4 a3 = *(const float4*)(sx + (4*ty+3) * KC + k);
            float4 b0 = *(const float4*)(sw + (k+0) * OUT_F + 4*tx);
            float4 b1 = *(const float4*)(sw + (k+1) * OUT_F + 4*tx);
            float4 b2 = *(const float4*)(sw + (k+2) * OUT_F + 4*tx);
            float4 b3 = *(const float4*)(sw + (k+3) * OUT_F + 4*tx);

            #define FMA4(A, AK, B) \
                A.x = fmaf(AK, B.x, A.x); A.y = fmaf(AK, B.y, A.y); \
                A.z = fmaf(AK, B.z, A.z); A.w = fmaf(AK, B.w, A.w);
            FMA4(acc0, a0.x, b0) FMA4(acc0, a0.y, b1) FMA4(acc0, a0.z, b2) FMA4(acc0, a0.w, b3)
            FMA4(acc1, a1.x, b0) FMA4(acc1, a1.y, b1) FMA4(acc1, a1.z, b2) FMA4(acc1, a1.w, b3)
            FMA4(acc2, a2.x, b0) FMA4(acc2, a2.y, b1) FMA4(acc2, a2.z, b2) FMA4(acc2, a2.w, b3)
            FMA4(acc3, a3.x, b0) FMA4(acc3, a3.y, b1) FMA4(acc3, a3.z, b2) FMA4(acc3, a3.w, b3)
            #undef FMA4
        }
    }

    #pragma unroll
    for (int rr = 0; rr < 4; rr++) {
        int n = node0 + 4*ty + rr;
        if (n < N_NODES) {
            float nm = g_norm[n];
            float4 a = rr==0 ? acc0 : rr==1 ? acc1 : rr==2 ? acc2 : acc3;
            g_featH[(size_t)n * 32 + 2*tx    ] = __floats2half2_rn(a.x * nm, a.y * nm);
            g_featH[(size_t)n * 32 + 2*tx + 1] = __floats2half2_rn(a.z * nm, a.w * nm);
        }
    }
}

// ---------------------------------------------------------------------------
// Warp-per-node gather, 4 edges per LDG.128 (unchanged from round 8/9).
// ---------------------------------------------------------------------------
__device__ __forceinline__ void gather_core(const uint4* __restrict__ fin,
                                            int start, int end, int lane,
                                            float* acc) {
    const int slot = lane >> 3;
    const int col8 = lane & 7;

    for (int j = start; j < end; j += 32) {
        int rem = end - j;
        int myidx = (lane < rem) ? g_esrc[j + lane] : 0;
        #pragma unroll
        for (int it = 0; it < 8; it++) {
            int es   = it * 4 + slot;
            int sidx = __shfl_sync(0xffffffffu, myidx, es);
            uint4 v  = fin[(size_t)sidx * 8 + col8];
            float w  = (es < rem) ? 1.f : 0.f;
            float2 p0 = __half22float2(*reinterpret_cast<__half2*>(&v.x));
            float2 p1 = __half22float2(*reinterpret_cast<__half2*>(&v.y));
            float2 p2 = __half22float2(*reinterpret_cast<__half2*>(&v.z));
            float2 p3 = __half22float2(*reinterpret_cast<__half2*>(&v.w));
            acc[0] = fmaf(w, p0.x, acc[0]);
            acc[1] = fmaf(w, p0.y, acc[1]);
            acc[2] = fmaf(w, p1.x, acc[2]);
            acc[3] = fmaf(w, p1.y, acc[3]);
            acc[4] = fmaf(w, p2.x, acc[4]);
            acc[5] = fmaf(w, p2.y, acc[5]);
            acc[6] = fmaf(w, p3.x, acc[6]);
            acc[7] = fmaf(w, p3.y, acc[7]);
        }
    }

    #pragma unroll
    for (int k = 0; k < 8; k++) {
        acc[k] += __shfl_xor_sync(0xffffffffu, acc[k], 8);
        acc[k] += __shfl_xor_sync(0xffffffffu, acc[k], 16);
    }
}

__device__ __forceinline__ void node_range(int node, int& start, int& end) {
    start = (node == 0) ? 0 : g_off[node - 1];
    end   = g_off[node];
}

// 5) step 1: g_feat2H[n] = half( norm^2 * sum g_featH[esrc] )
__global__ __launch_bounds__(256) void k_gather1() {
    int node = (blockIdx.x * 256 + threadIdx.x) >> 5;
    if (node >= N_NODES) return;
    int lane = threadIdx.x & 31;
    int start, end; node_range(node, start, end);

    float acc[8] = {0.f,0.f,0.f,0.f,0.f,0.f,0.f,0.f};
    gather_core((const uint4*)g_featH, start, end, lane, acc);

    if (lane < 8) {
        float nm = g_norm[node];
        float f  = nm * nm;
        uint4 o;
        __half2 h;
        h = __floats2half2_rn(acc[0]*f, acc[1]*f); o.x = *reinterpret_cast<unsigned*>(&h);
        h = __floats2half2_rn(acc[2]*f, acc[3]*f); o.y = *reinterpret_cast<unsigned*>(&h);
        h = __floats2half2_rn(acc[4]*f, acc[5]*f); o.z = *reinterpret_cast<unsigned*>(&h);
        h = __floats2half2_rn(acc[6]*f, acc[7]*f); o.w = *reinterpret_cast<unsigned*>(&h);
        ((uint4*)g_feat2H)[(size_t)node * 8 + lane] = o;
    }
}

// 6) step 2: out[n] = norm * sum g_feat2H[esrc] + b   (fp32 out)
__global__ __launch_bounds__(256) void k_gather2(float* __restrict__ out,
                                                 const float* __restrict__ bias) {
    int node = (blockIdx.x * 256 + threadIdx.x) >> 5;
    if (node >= N_NODES) return;
    int lane = threadIdx.x & 31;
    int start, end; node_range(node, start, end);

    float acc[8] = {0.f,0.f,0.f,0.f,0.f,0.f,0.f,0.f};
    gather_core((const uint4*)g_feat2H, start, end, lane, acc);

    if (lane < 8) {
        float nm = g_norm[node];
        const float4* b4 = (const float4*)bias;
        float4 bb0 = b4[lane * 2];
        float4 bb1 = b4[lane * 2 + 1];
        float4 r0, r1;
        r0.x = fmaf(acc[0], nm, bb0.x);
        r0.y = fmaf(acc[1], nm, bb0.y);
        r0.z = fmaf(acc[2], nm, bb0.z);
        r0.w = fmaf(acc[3], nm, bb0.w);
        r1.x = fmaf(acc[4], nm, bb1.x);
        r1.y = fmaf(acc[5], nm, bb1.y);
        r1.z = fmaf(acc[6], nm, bb1.z);
        r1.w = fmaf(acc[7], nm, bb1.w);
        float4* o4 = (float4*)out;
        o4[(size_t)node * 16 + lane * 2    ] = r0;
        o4[(size_t)node * 16 + lane * 2 + 1] = r1;
    }
}

// ---------------------------------------------------------------------------
// Launch: zero(1), deg(2), scan(3), gemm_csr(4 <- PROFILED), g1(5), g2(6)
// ---------------------------------------------------------------------------
extern "C" void kernel_launch(void* const* d_in, const int* in_sizes, int n_in,
                              void* d_out, int out_size) {
    const float* x   = (const float*)d_in[0];
    const int*   src = (const int*)  d_in[1];
    const int*   dst = (const int*)  d_in[2];
    const float* W   = (const float*)d_in[3];
    const float* b   = (const float*)d_in[4];
    float*       out = (float*)d_out;

    k_zero<<<(NPAD / 4 + 255) / 256, 256>>>();
    k_deg <<<(N_EDGES + 255) / 256, 256>>>(dst);
    k_scan<<<1, 1024>>>();
    k_gemm_csr<<<FUSED_BLOCKS, 256>>>(x, W, src, dst);

    int gather_blocks = (N_NODES * 32 + 255) / 256;   // warp per node
    k_gather1<<<gather_blocks, 256>>>();
    k_gather2<<<gather_blocks, 256>>>(out, b);
}